// round 4
// baseline (speedup 1.0000x reference)
#include <cuda_runtime.h>
#include <math.h>
#include <float.h>

#define NPTS 16384
#define DIM  512
#define KC   1024
#define KD   (KC * DIM)
#define ITERS 10

// Fixed-point scales for deterministic integer-atomic accumulation.
#define SCALE_SUM   4294967296.0      // 2^32  (signed values, |x| small)
#define SCALE_DIST  68719476736.0     // 2^36  (non-negative residual^2 sums)

// ---------------- device scratch (no allocations allowed) ----------------
__device__ float              g_centroids[KD];
__device__ float              g_xsq[NPTS];
__device__ float              g_csq[KC];
__device__ int                g_clusters[NPTS];
__device__ unsigned long long g_sums[KD];    // fixed-point centroid sums
__device__ int                g_counts[KC];
__device__ unsigned long long g_dacc[KD];    // fixed-point residual^2 sums
__device__ double             g_pA[512];
__device__ double             g_pB[512];
__device__ double             g_pC[512];
__device__ double             g_scal[2];     // [0]=sum p, [1]=sum log(p2+eps)

// ---------------- row squared norms ----------------
__global__ void k_xsq(const float* __restrict__ feats) {
    int w    = (blockIdx.x * blockDim.x + threadIdx.x) >> 5;
    int lane = threadIdx.x & 31;
    if (w >= NPTS) return;
    const float* r = feats + (size_t)w * DIM;
    float s = 0.f;
    #pragma unroll
    for (int i = 0; i < DIM / 32; i++) { float v = r[lane + i * 32]; s += v * v; }
    #pragma unroll
    for (int o = 16; o; o >>= 1) s += __shfl_xor_sync(0xffffffffu, s, o);
    if (lane == 0) g_xsq[w] = s;
}

__global__ void k_csq() {
    int w    = (blockIdx.x * blockDim.x + threadIdx.x) >> 5;
    int lane = threadIdx.x & 31;
    if (w >= KC) return;
    const float* r = g_centroids + (size_t)w * DIM;
    float s = 0.f;
    #pragma unroll
    for (int i = 0; i < DIM / 32; i++) { float v = r[lane + i * 32]; s += v * v; }
    #pragma unroll
    for (int o = 16; o; o >>= 1) s += __shfl_xor_sync(0xffffffffu, s, o);
    if (lane == 0) g_csq[w] = s;
}

// ---------------- init centroids = feats[:K] (contiguous) ----------------
__global__ void k_copy_init(const float* __restrict__ feats) {
    int i = blockIdx.x * blockDim.x + threadIdx.x;
    if (i < KD) g_centroids[i] = feats[i];
}

// ---------------- fused distance-GEMM + argmin ----------------
// Block tile: 128 points x 64 clusters, BK=16, 256 threads, 8x4 per thread.
__global__ __launch_bounds__(256)
void k_assign(const float* __restrict__ A) {
    __shared__ float As[16][132];   // padded; row base stays 16B-aligned (132*4=528=33*16)
    __shared__ float Bs[16][68];    // 68*4=272=17*16

    const float* B = g_centroids;
    int tid  = threadIdx.x;
    int tx   = tid & 15;
    int ty   = tid >> 4;
    int m0   = blockIdx.x * 128;
    int arow = tid >> 2;            // 0..63
    int acol = (tid & 3) << 2;      // 0,4,8,12

    float xrow[8];
    #pragma unroll
    for (int i = 0; i < 8; i++) xrow[i] = g_xsq[m0 + ty * 8 + i];

    float best[8];
    int   bidx[8];
    #pragma unroll
    for (int i = 0; i < 8; i++) { best[i] = FLT_MAX; bidx[i] = 0; }

    for (int n0 = 0; n0 < KC; n0 += 64) {
        float acc[8][4];
        #pragma unroll
        for (int i = 0; i < 8; i++)
            #pragma unroll
            for (int j = 0; j < 4; j++) acc[i][j] = 0.f;

        for (int k0 = 0; k0 < DIM; k0 += 16) {
            #pragma unroll
            for (int r = 0; r < 2; r++) {
                int row = arow + r * 64;
                float4 v = *(const float4*)(A + (size_t)(m0 + row) * DIM + k0 + acol);
                As[acol + 0][row] = v.x; As[acol + 1][row] = v.y;
                As[acol + 2][row] = v.z; As[acol + 3][row] = v.w;
            }
            {
                float4 v = *(const float4*)(B + (size_t)(n0 + arow) * DIM + k0 + acol);
                Bs[acol + 0][arow] = v.x; Bs[acol + 1][arow] = v.y;
                Bs[acol + 2][arow] = v.z; Bs[acol + 3][arow] = v.w;
            }
            __syncthreads();
            #pragma unroll
            for (int kk = 0; kk < 16; kk++) {
                float4 a0 = *(const float4*)&As[kk][ty * 8];
                float4 a1 = *(const float4*)&As[kk][ty * 8 + 4];
                float4 bb = *(const float4*)&Bs[kk][tx * 4];
                float a[8] = {a0.x, a0.y, a0.z, a0.w, a1.x, a1.y, a1.z, a1.w};
                float b[4] = {bb.x, bb.y, bb.z, bb.w};
                #pragma unroll
                for (int i = 0; i < 8; i++)
                    #pragma unroll
                    for (int j = 0; j < 4; j++)
                        acc[i][j] = fmaf(a[i], b[j], acc[i][j]);
            }
            __syncthreads();
        }

        // distances + running argmin (ascending n, strict < => first-min semantics)
        #pragma unroll
        for (int i = 0; i < 8; i++) {
            #pragma unroll
            for (int j = 0; j < 4; j++) {
                int   n  = n0 + tx * 4 + j;
                float dd = xrow[i] - 2.0f * acc[i][j] + g_csq[n];
                if (dd < best[i]) { best[i] = dd; bidx[i] = n; }
            }
        }
    }

    // reduce across the 16 tx-lanes of this row group (stays within half-warp)
    #pragma unroll
    for (int i = 0; i < 8; i++) {
        float bv = best[i];
        int   bi = bidx[i];
        #pragma unroll
        for (int o = 8; o; o >>= 1) {
            float ov = __shfl_xor_sync(0xffffffffu, bv, o);
            int   oi = __shfl_xor_sync(0xffffffffu, bi, o);
            if (ov < bv || (ov == bv && oi < bi)) { bv = ov; bi = oi; }
        }
        if (tx == 0) g_clusters[m0 + ty * 8 + i] = bi;
    }
}

// ---------------- clears ----------------
__global__ void k_clear_sums() {
    int i = blockIdx.x * blockDim.x + threadIdx.x;
    if (i < KD) g_sums[i] = 0ull;
    if (i < KC) g_counts[i] = 0;
}
__global__ void k_clear_dacc() {
    int i = blockIdx.x * blockDim.x + threadIdx.x;
    if (i < KD) g_dacc[i] = 0ull;
}

// ---------------- deterministic segment sums (fixed-point int atomics) ----------------
__global__ void k_accum(const float* __restrict__ feats) {
    int p = blockIdx.x;
    int c = g_clusters[p];
    const float* f = feats + (size_t)p * DIM;
    unsigned long long* srow = g_sums + (size_t)c * DIM;
    for (int d = threadIdx.x; d < DIM; d += blockDim.x) {
        long long q = __double2ll_rn((double)f[d] * SCALE_SUM);
        atomicAdd(&srow[d], (unsigned long long)q);
    }
    if (threadIdx.x == 0) atomicAdd(&g_counts[c], 1);
}

__global__ void k_update() {
    int i = blockIdx.x * blockDim.x + threadIdx.x;
    if (i >= KD) return;
    int k   = i >> 9;          // DIM = 512
    int cnt = g_counts[k];
    if (cnt > 0) {
        double s = (double)(long long)g_sums[i] * (1.0 / SCALE_SUM);
        g_centroids[i] = (float)(s / (double)cnt);
    }
}

__global__ void k_resid(const float* __restrict__ feats) {
    int p = blockIdx.x;
    int c = g_clusters[p];
    const float* f  = feats + (size_t)p * DIM;
    const float* cc = g_centroids + (size_t)c * DIM;
    unsigned long long* drow = g_dacc + (size_t)c * DIM;
    for (int d = threadIdx.x; d < DIM; d += blockDim.x) {
        float r  = f[d] - cc[d];
        float r2 = r * r;                 // squared in fp32, like reference
        long long q = __double2ll_rn((double)r2 * SCALE_DIST);
        atomicAdd(&drow[d], (unsigned long long)q);
    }
}

// ---------------- final reductions (deterministic fixed-order trees) ----------------
__global__ void k_reduce1() {
    __shared__ double sa[256], sb[256];
    int t    = threadIdx.x;
    int base = blockIdx.x * 1024;
    double la = 0.0, lb = 0.0;
    #pragma unroll
    for (int e = 0; e < 4; e++) {
        int i = base + t + e * 256;
        float dist = (float)((double)(long long)g_dacc[i] * (1.0 / SCALE_DIST));
        float p1 = expf(dist * -10.0f);   // 1/CONCENTRATION
        float p2 = expf(dist * -10.0f);   // 1/TEMPERATURE
        la += (double)p1;
        lb += (double)logf(p2 + 1e-6f);
    }
    sa[t] = la; sb[t] = lb;
    __syncthreads();
    for (int s = 128; s; s >>= 1) {
        if (t < s) { sa[t] += sa[t + s]; sb[t] += sb[t + s]; }
        __syncthreads();
    }
    if (t == 0) { g_pA[blockIdx.x] = sa[0]; g_pB[blockIdx.x] = sb[0]; }
}

__global__ void k_final1() {
    __shared__ double sa[512], sb[512];
    int t = threadIdx.x;
    sa[t] = g_pA[t]; sb[t] = g_pB[t];
    __syncthreads();
    for (int s = 256; s; s >>= 1) {
        if (t < s) { sa[t] += sa[t + s]; sb[t] += sb[t + s]; }
        __syncthreads();
    }
    if (t == 0) { g_scal[0] = sa[0]; g_scal[1] = sb[0]; }
}

__global__ void k_reduce2() {
    __shared__ double sc[256];
    int t    = threadIdx.x;
    int base = blockIdx.x * 1024;
    float S  = (float)g_scal[0];
    double lc = 0.0;
    #pragma unroll
    for (int e = 0; e < 4; e++) {
        int i = base + t + e * 256;
        float dist = (float)((double)(long long)g_dacc[i] * (1.0 / SCALE_DIST));
        float p1 = expf(dist * -10.0f);
        float q  = p1 / S;
        lc += (double)(q * logf(q + 1e-6f));
    }
    sc[t] = lc;
    __syncthreads();
    for (int s = 128; s; s >>= 1) {
        if (t < s) sc[t] += sc[t + s];
        __syncthreads();
    }
    if (t == 0) g_pC[blockIdx.x] = sc[0];
}

__global__ void k_final2(float* __restrict__ out) {
    __shared__ double sc[512];
    int t = threadIdx.x;
    sc[t] = g_pC[t];
    __syncthreads();
    for (int s = 256; s; s >>= 1) {
        if (t < s) sc[t] += sc[t + s];
        __syncthreads();
    }
    if (t == 0) {
        double ent = sc[0] / (double)KD;           // / NUM_CLUSTER_ITERS (=1)
        double nll = -(g_scal[1] / (double)KD);
        out[0] = (float)(ent + nll);
    }
}

// ---------------- launch ----------------
extern "C" void kernel_launch(void* const* d_in, const int* in_sizes, int n_in,
                              void* d_out, int out_size) {
    (void)in_sizes; (void)n_in; (void)out_size;
    const float* feats = (const float*)d_in[0];
    float* out = (float*)d_out;

    k_xsq<<<NPTS / 8, 256>>>(feats);
    k_copy_init<<<KD / 256, 256>>>(feats);

    for (int it = 0; it < ITERS; ++it) {
        k_csq<<<KC / 8, 256>>>();
        k_assign<<<NPTS / 128, 256>>>(feats);
        k_clear_sums<<<KD / 256, 256>>>();
        k_accum<<<NPTS, 128>>>(feats);
        k_update<<<KD / 256, 256>>>();
    }

    k_csq<<<KC / 8, 256>>>();
    k_assign<<<NPTS / 128, 256>>>(feats);
    k_clear_dacc<<<KD / 256, 256>>>();
    k_resid<<<NPTS, 128>>>(feats);

    k_reduce1<<<512, 256>>>();
    k_final1<<<1, 512>>>();
    k_reduce2<<<512, 256>>>();
    k_final2<<<1, 512>>>(out);
}

// round 5
// speedup vs baseline: 2.0930x; 2.0930x over previous
#include <cuda_runtime.h>
#include <math.h>
#include <float.h>

#define NPTS 16384
#define DIM  512
#define KC   1024
#define KD   (KC * DIM)
#define ITERS 10

// Fixed-point scales for deterministic integer-atomic accumulation.
#define SCALE_SUM   4294967296.0      // 2^32  (signed values, |x| small)
#define SCALE_DIST  68719476736.0     // 2^36  (non-negative residual^2 sums)

// ---------------- device scratch (no allocations allowed) ----------------
__device__ float              g_centroids[KD];
__device__ float              g_xsq[NPTS];
__device__ float              g_csq[KC];
__device__ unsigned long long g_best[NPTS];  // packed (ordered dist)<<32 | idx
__device__ unsigned long long g_sums[KD];    // fixed-point centroid sums
__device__ int                g_counts[KC];
__device__ unsigned long long g_dacc[KD];    // fixed-point residual^2 sums
__device__ double             g_pA[512];
__device__ double             g_pB[512];
__device__ double             g_pC[512];
__device__ double             g_scal[2];     // [0]=sum p, [1]=sum log(p2+eps)

// ---------------- packed f32x2 helpers (FFMA2 path, PTX-only) ----------------
__device__ __forceinline__ void ffma2(unsigned long long& acc,
                                      unsigned long long a,
                                      unsigned long long b) {
    asm("fma.rn.f32x2 %0, %1, %2, %0;" : "+l"(acc) : "l"(a), "l"(b));
}
__device__ __forceinline__ unsigned long long dup2(float x) {
    unsigned long long r;
    asm("mov.b64 %0, {%1, %1};" : "=l"(r) : "f"(x));
    return r;
}

// ---------------- row squared norms ----------------
__global__ void k_xsq(const float* __restrict__ feats) {
    int w    = (blockIdx.x * blockDim.x + threadIdx.x) >> 5;
    int lane = threadIdx.x & 31;
    if (w >= NPTS) return;
    const float* r = feats + (size_t)w * DIM;
    float s = 0.f;
    #pragma unroll
    for (int i = 0; i < DIM / 32; i++) { float v = r[lane + i * 32]; s += v * v; }
    #pragma unroll
    for (int o = 16; o; o >>= 1) s += __shfl_xor_sync(0xffffffffu, s, o);
    if (lane == 0) g_xsq[w] = s;
}

__global__ void k_csq() {
    int w    = (blockIdx.x * blockDim.x + threadIdx.x) >> 5;
    int lane = threadIdx.x & 31;
    if (w >= KC) return;
    const float* r = g_centroids + (size_t)w * DIM;
    float s = 0.f;
    #pragma unroll
    for (int i = 0; i < DIM / 32; i++) { float v = r[lane + i * 32]; s += v * v; }
    #pragma unroll
    for (int o = 16; o; o >>= 1) s += __shfl_xor_sync(0xffffffffu, s, o);
    if (lane == 0) g_csq[w] = s;
}

// ---------------- init centroids = feats[:K] (contiguous) ----------------
__global__ void k_copy_init(const float* __restrict__ feats) {
    int i = blockIdx.x * blockDim.x + threadIdx.x;
    if (i < KD) g_centroids[i] = feats[i];
}

__global__ void k_clear_best() {
    int i = blockIdx.x * blockDim.x + threadIdx.x;
    if (i < NPTS) g_best[i] = 0xFFFFFFFFFFFFFFFFull;
}

// ---------------- fused distance-GEMM + argmin (FFMA2, 128x128 tiles) ------
// grid (NPTS/128, 4): each block handles 128 points x 256 clusters.
// 256 threads, per-thread 8x8, accumulators packed f32x2 along rows.
__global__ __launch_bounds__(256, 2)
void k_assign(const float* __restrict__ A) {
    __shared__ float As[16][132];   // k-major, 132*4=528B rows (16B aligned)
    __shared__ float Bs[16][132];

    const float* Bmat = g_centroids;
    int tid   = threadIdx.x;
    int tx    = tid & 15;           // 0..15  (cluster axis)
    int ty    = tid >> 4;           // 0..15  (point axis)
    int m0    = blockIdx.x * 128;
    int nbase = blockIdx.y * 256;

    int frow  = tid >> 1;           // 0..127 fill row
    int fcol  = (tid & 1) * 8;      // 0 or 8 fill col group

    float xr[8];
    #pragma unroll
    for (int i = 0; i < 8; i++) xr[i] = g_xsq[m0 + ty * 8 + i];

    float best[8];
    int   bidx[8];
    #pragma unroll
    for (int i = 0; i < 8; i++) { best[i] = FLT_MAX; bidx[i] = 0; }

    for (int n0 = 0; n0 < 256; n0 += 128) {
        unsigned long long acc2[4][8];
        #pragma unroll
        for (int p = 0; p < 4; p++)
            #pragma unroll
            for (int j = 0; j < 8; j++) acc2[p][j] = 0ull;

        for (int k0 = 0; k0 < DIM; k0 += 16) {
            {
                const float* ap = A + (size_t)(m0 + frow) * DIM + k0 + fcol;
                float4 a0 = *(const float4*)ap;
                float4 a1 = *(const float4*)(ap + 4);
                As[fcol + 0][frow] = a0.x; As[fcol + 1][frow] = a0.y;
                As[fcol + 2][frow] = a0.z; As[fcol + 3][frow] = a0.w;
                As[fcol + 4][frow] = a1.x; As[fcol + 5][frow] = a1.y;
                As[fcol + 6][frow] = a1.z; As[fcol + 7][frow] = a1.w;
            }
            {
                const float* bp = Bmat + (size_t)(nbase + n0 + frow) * DIM + k0 + fcol;
                float4 b0 = *(const float4*)bp;
                float4 b1 = *(const float4*)(bp + 4);
                Bs[fcol + 0][frow] = b0.x; Bs[fcol + 1][frow] = b0.y;
                Bs[fcol + 2][frow] = b0.z; Bs[fcol + 3][frow] = b0.w;
                Bs[fcol + 4][frow] = b1.x; Bs[fcol + 5][frow] = b1.y;
                Bs[fcol + 6][frow] = b1.z; Bs[fcol + 7][frow] = b1.w;
            }
            __syncthreads();
            #pragma unroll
            for (int kk = 0; kk < 16; kk++) {
                unsigned long long a2[4];
                #pragma unroll
                for (int p = 0; p < 4; p++)
                    a2[p] = *(const unsigned long long*)&As[kk][ty * 8 + 2 * p];
                float4 bv0 = *(const float4*)&Bs[kk][tx * 4];
                float4 bv1 = *(const float4*)&Bs[kk][64 + tx * 4];
                float bv[8] = {bv0.x, bv0.y, bv0.z, bv0.w,
                               bv1.x, bv1.y, bv1.z, bv1.w};
                #pragma unroll
                for (int j = 0; j < 8; j++) {
                    unsigned long long bd = dup2(bv[j]);
                    #pragma unroll
                    for (int p = 0; p < 4; p++) ffma2(acc2[p][j], a2[p], bd);
                }
            }
            __syncthreads();
        }

        // distances + running argmin. Per-thread col order is strictly
        // ascending (j<4: tx*4+j; j>=4: 64+tx*4+(j-4); tiles ascending),
        // so strict < gives first-min semantics within the thread.
        #pragma unroll
        for (int j = 0; j < 8; j++) {
            int col = nbase + n0 + ((j < 4) ? (tx * 4 + j)
                                            : (64 + tx * 4 + (j - 4)));
            float cs = g_csq[col];
            #pragma unroll
            for (int p = 0; p < 4; p++) {
                float d0, d1;
                asm("mov.b64 {%0, %1}, %2;" : "=f"(d0), "=f"(d1) : "l"(acc2[p][j]));
                float dist0 = xr[2 * p]     - 2.0f * d0 + cs;
                float dist1 = xr[2 * p + 1] - 2.0f * d1 + cs;
                if (dist0 < best[2 * p])     { best[2 * p]     = dist0; bidx[2 * p]     = col; }
                if (dist1 < best[2 * p + 1]) { best[2 * p + 1] = dist1; bidx[2 * p + 1] = col; }
            }
        }
    }

    // reduce across the 16 tx-lanes (stays within half-warp), then combine
    // across K-quarter blocks with a deterministic packed atomicMin.
    #pragma unroll
    for (int i = 0; i < 8; i++) {
        float bv = best[i];
        int   bi = bidx[i];
        #pragma unroll
        for (int o = 8; o; o >>= 1) {
            float ov = __shfl_xor_sync(0xffffffffu, bv, o);
            int   oi = __shfl_xor_sync(0xffffffffu, bi, o);
            if (ov < bv || (ov == bv && oi < bi)) { bv = ov; bi = oi; }
        }
        if (tx == 0) {
            unsigned int u = __float_as_uint(bv);
            u = (u & 0x80000000u) ? ~u : (u | 0x80000000u);  // order-preserving
            unsigned long long key = ((unsigned long long)u << 32) |
                                     (unsigned int)bi;
            atomicMin(&g_best[m0 + ty * 8 + i], key);
        }
    }
}

// ---------------- clears ----------------
__global__ void k_clear_sums() {
    int i = blockIdx.x * blockDim.x + threadIdx.x;
    if (i < KD) g_sums[i] = 0ull;
    if (i < KC) g_counts[i] = 0;
}
__global__ void k_clear_dacc() {
    int i = blockIdx.x * blockDim.x + threadIdx.x;
    if (i < KD) g_dacc[i] = 0ull;
}

// ---------------- deterministic segment sums (fixed-point int atomics) -----
__global__ void k_accum(const float* __restrict__ feats) {
    int p = blockIdx.x;
    int c = (int)(unsigned int)(g_best[p] & 0xFFFFFFFFull);
    const float* f = feats + (size_t)p * DIM;
    unsigned long long* srow = g_sums + (size_t)c * DIM;
    for (int d = threadIdx.x; d < DIM; d += blockDim.x) {
        long long q = __double2ll_rn((double)f[d] * SCALE_SUM);
        atomicAdd(&srow[d], (unsigned long long)q);
    }
    if (threadIdx.x == 0) atomicAdd(&g_counts[c], 1);
}

__global__ void k_update() {
    int i = blockIdx.x * blockDim.x + threadIdx.x;
    if (i >= KD) return;
    int k   = i >> 9;          // DIM = 512
    int cnt = g_counts[k];
    if (cnt > 0) {
        double s = (double)(long long)g_sums[i] * (1.0 / SCALE_SUM);
        g_centroids[i] = (float)(s / (double)cnt);
    }
}

__global__ void k_resid(const float* __restrict__ feats) {
    int p = blockIdx.x;
    int c = (int)(unsigned int)(g_best[p] & 0xFFFFFFFFull);
    const float* f  = feats + (size_t)p * DIM;
    const float* cc = g_centroids + (size_t)c * DIM;
    unsigned long long* drow = g_dacc + (size_t)c * DIM;
    for (int d = threadIdx.x; d < DIM; d += blockDim.x) {
        float r  = f[d] - cc[d];
        float r2 = r * r;                 // squared in fp32, like reference
        long long q = __double2ll_rn((double)r2 * SCALE_DIST);
        atomicAdd(&drow[d], (unsigned long long)q);
    }
}

// ---------------- final reductions (deterministic fixed-order trees) -------
__global__ void k_reduce1() {
    __shared__ double sa[256], sb[256];
    int t    = threadIdx.x;
    int base = blockIdx.x * 1024;
    double la = 0.0, lb = 0.0;
    #pragma unroll
    for (int e = 0; e < 4; e++) {
        int i = base + t + e * 256;
        float dist = (float)((double)(long long)g_dacc[i] * (1.0 / SCALE_DIST));
        float p1 = expf(dist * -10.0f);   // 1/CONCENTRATION
        float p2 = expf(dist * -10.0f);   // 1/TEMPERATURE
        la += (double)p1;
        lb += (double)logf(p2 + 1e-6f);
    }
    sa[t] = la; sb[t] = lb;
    __syncthreads();
    for (int s = 128; s; s >>= 1) {
        if (t < s) { sa[t] += sa[t + s]; sb[t] += sb[t + s]; }
        __syncthreads();
    }
    if (t == 0) { g_pA[blockIdx.x] = sa[0]; g_pB[blockIdx.x] = sb[0]; }
}

__global__ void k_final1() {
    __shared__ double sa[512], sb[512];
    int t = threadIdx.x;
    sa[t] = g_pA[t]; sb[t] = g_pB[t];
    __syncthreads();
    for (int s = 256; s; s >>= 1) {
        if (t < s) { sa[t] += sa[t + s]; sb[t] += sb[t + s]; }
        __syncthreads();
    }
    if (t == 0) { g_scal[0] = sa[0]; g_scal[1] = sb[0]; }
}

__global__ void k_reduce2() {
    __shared__ double sc[256];
    int t    = threadIdx.x;
    int base = blockIdx.x * 1024;
    float S  = (float)g_scal[0];
    double lc = 0.0;
    #pragma unroll
    for (int e = 0; e < 4; e++) {
        int i = base + t + e * 256;
        float dist = (float)((double)(long long)g_dacc[i] * (1.0 / SCALE_DIST));
        float p1 = expf(dist * -10.0f);
        float q  = p1 / S;
        lc += (double)(q * logf(q + 1e-6f));
    }
    sc[t] = lc;
    __syncthreads();
    for (int s = 128; s; s >>= 1) {
        if (t < s) sc[t] += sc[t + s];
        __syncthreads();
    }
    if (t == 0) g_pC[blockIdx.x] = sc[0];
}

__global__ void k_final2(float* __restrict__ out) {
    __shared__ double sc[512];
    int t = threadIdx.x;
    sc[t] = g_pC[t];
    __syncthreads();
    for (int s = 256; s; s >>= 1) {
        if (t < s) sc[t] += sc[t + s];
        __syncthreads();
    }
    if (t == 0) {
        double ent = sc[0] / (double)KD;           // / NUM_CLUSTER_ITERS (=1)
        double nll = -(g_scal[1] / (double)KD);
        out[0] = (float)(ent + nll);
    }
}

// ---------------- launch ----------------
extern "C" void kernel_launch(void* const* d_in, const int* in_sizes, int n_in,
                              void* d_out, int out_size) {
    (void)in_sizes; (void)n_in; (void)out_size;
    const float* feats = (const float*)d_in[0];
    float* out = (float*)d_out;

    k_xsq<<<NPTS / 8, 256>>>(feats);
    k_copy_init<<<KD / 256, 256>>>(feats);

    for (int it = 0; it < ITERS; ++it) {
        k_csq<<<KC / 8, 256>>>();
        k_clear_best<<<NPTS / 256, 256>>>();
        k_assign<<<dim3(NPTS / 128, 4), 256>>>(feats);
        k_clear_sums<<<KD / 256, 256>>>();
        k_accum<<<NPTS, 128>>>(feats);
        k_update<<<KD / 256, 256>>>();
    }

    k_csq<<<KC / 8, 256>>>();
    k_clear_best<<<NPTS / 256, 256>>>();
    k_assign<<<dim3(NPTS / 128, 4), 256>>>(feats);
    k_clear_dacc<<<KD / 256, 256>>>();
    k_resid<<<NPTS, 128>>>(feats);

    k_reduce1<<<512, 256>>>();
    k_final1<<<1, 512>>>();
    k_reduce2<<<512, 256>>>();
    k_final2<<<1, 512>>>(out);
}

// round 8
// speedup vs baseline: 2.7477x; 1.3128x over previous
#include <cuda_runtime.h>
#include <math.h>
#include <float.h>
#include <stdint.h>

#define NPTS 16384
#define DIM  512
#define KC   1024
#define KD   (KC * DIM)
#define ITERS 10

// Fixed-point scales for deterministic integer-atomic accumulation.
#define SCALE_SUM   4294967296.0      // 2^32
#define SCALE_DIST  68719476736.0     // 2^36

// ---------------- device scratch (no allocations allowed) ----------------
__device__ float              g_centroids[KD];
__device__ float              g_xsq[NPTS];
__device__ float              g_csq[KC];
__device__ unsigned long long g_best[NPTS];  // packed (ordered dist)<<32 | idx
__device__ unsigned long long g_sums[KD];
__device__ int                g_counts[KC];
__device__ unsigned long long g_dacc[KD];
__device__ double             g_pA[512];
__device__ double             g_pB[512];
__device__ double             g_pC[512];
__device__ double             g_scal[2];

// k-major transposed operands: g_At[d][n] = feats[n][d], g_Bt[d][k] = centroids[k][d]
__device__ float g_At[DIM * NPTS];
__device__ float g_Bt[DIM * KC];

// ---------------- packed f32x2 helpers (FFMA2 path, PTX-only) ----------------
__device__ __forceinline__ void ffma2(unsigned long long& acc,
                                      unsigned long long a,
                                      unsigned long long b) {
    asm("fma.rn.f32x2 %0, %1, %2, %0;" : "+l"(acc) : "l"(a), "l"(b));
}
__device__ __forceinline__ unsigned long long dup2(float x) {
    unsigned long long r;
    asm("mov.b64 %0, {%1, %1};" : "=l"(r) : "f"(x));
    return r;
}
__device__ __forceinline__ uint32_t smem_u32(const void* p) {
    uint32_t a;
    asm("{ .reg .u64 t; cvta.to.shared.u64 t, %1; cvt.u32.u64 %0, t; }"
        : "=r"(a) : "l"(p));
    return a;
}
__device__ __forceinline__ void cp16(uint32_t dst, const void* src) {
    asm volatile("cp.async.cg.shared.global [%0], [%1], 16;"
                 :: "r"(dst), "l"(src));
}
#define CP_COMMIT()  asm volatile("cp.async.commit_group;" ::: "memory")
#define CP_WAIT1()   asm volatile("cp.async.wait_group 1;" ::: "memory")
#define CP_WAIT0()   asm volatile("cp.async.wait_group 0;" ::: "memory")

// ---------------- transposes ----------------
// feats [NPTS, DIM] -> g_At [DIM, NPTS]
__global__ void k_transpose_A(const float* __restrict__ feats) {
    __shared__ float t[32][33];
    int bx = blockIdx.x * 32;   // dim offset
    int by = blockIdx.y * 32;   // point offset
    int tx = threadIdx.x, ty = threadIdx.y;   // (32, 8)
    #pragma unroll
    for (int r = 0; r < 4; r++)
        t[ty + r * 8][tx] = feats[(size_t)(by + ty + r * 8) * DIM + bx + tx];
    __syncthreads();
    #pragma unroll
    for (int r = 0; r < 4; r++)
        g_At[(size_t)(bx + ty + r * 8) * NPTS + by + tx] = t[tx][ty + r * 8];
}
// g_centroids [KC, DIM] -> g_Bt [DIM, KC]
__global__ void k_transpose_B() {
    __shared__ float t[32][33];
    int bx = blockIdx.x * 32;   // dim offset
    int by = blockIdx.y * 32;   // cluster offset
    int tx = threadIdx.x, ty = threadIdx.y;
    #pragma unroll
    for (int r = 0; r < 4; r++)
        t[ty + r * 8][tx] = g_centroids[(size_t)(by + ty + r * 8) * DIM + bx + tx];
    __syncthreads();
    #pragma unroll
    for (int r = 0; r < 4; r++)
        g_Bt[(size_t)(bx + ty + r * 8) * KC + by + tx] = t[tx][ty + r * 8];
}

// ---------------- row squared norms ----------------
__global__ void k_xsq(const float* __restrict__ feats) {
    int w    = (blockIdx.x * blockDim.x + threadIdx.x) >> 5;
    int lane = threadIdx.x & 31;
    if (w >= NPTS) return;
    const float* r = feats + (size_t)w * DIM;
    float s = 0.f;
    #pragma unroll
    for (int i = 0; i < DIM / 32; i++) { float v = r[lane + i * 32]; s += v * v; }
    #pragma unroll
    for (int o = 16; o; o >>= 1) s += __shfl_xor_sync(0xffffffffu, s, o);
    if (lane == 0) g_xsq[w] = s;
}
__global__ void k_csq() {
    int w    = (blockIdx.x * blockDim.x + threadIdx.x) >> 5;
    int lane = threadIdx.x & 31;
    if (w >= KC) return;
    const float* r = g_centroids + (size_t)w * DIM;
    float s = 0.f;
    #pragma unroll
    for (int i = 0; i < DIM / 32; i++) { float v = r[lane + i * 32]; s += v * v; }
    #pragma unroll
    for (int o = 16; o; o >>= 1) s += __shfl_xor_sync(0xffffffffu, s, o);
    if (lane == 0) g_csq[w] = s;
}

__global__ void k_copy_init(const float* __restrict__ feats) {
    int i = blockIdx.x * blockDim.x + threadIdx.x;
    if (i < KD) g_centroids[i] = feats[i];
}
__global__ void k_clear_best() {
    int i = blockIdx.x * blockDim.x + threadIdx.x;
    if (i < NPTS) g_best[i] = 0xFFFFFFFFFFFFFFFFull;
}

// ---------------- fused distance-GEMM + argmin -----------------------------
// grid (NPTS/128, KC/128), 256 threads, 2 CTAs/SM. FFMA2 mainloop with
// double-buffered cp.async tiles from k-major g_At/g_Bt.
__global__ __launch_bounds__(256, 2)
void k_assign(void) {
    __shared__ float As[2][16][128];
    __shared__ float Bs[2][16][128];

    int tid   = threadIdx.x;
    int tx    = tid & 15;           // 0..15 (cluster axis)
    int ty    = tid >> 4;           // 0..15 (point axis)
    int m0    = blockIdx.x * 128;
    int nbase = blockIdx.y * 128;

    int frow = tid >> 4;            // 0..15 fill row (k within chunk)
    int fs   = (tid & 15) * 2;      // 16B segment pair within 512B row

    float xr[8];
    #pragma unroll
    for (int i = 0; i < 8; i++) xr[i] = g_xsq[m0 + ty * 8 + i];

    unsigned long long acc2[4][8];
    #pragma unroll
    for (int p = 0; p < 4; p++)
        #pragma unroll
        for (int j = 0; j < 8; j++) acc2[p][j] = 0ull;

    uint32_t aDst0 = smem_u32(&As[0][frow][fs * 4]);
    uint32_t bDst0 = smem_u32(&Bs[0][frow][fs * 4]);

    // prologue: chunk 0 -> buffer 0
    {
        const float* asrc = g_At + (size_t)frow * NPTS + m0 + fs * 4;
        const float* bsrc = g_Bt + (size_t)frow * KC + nbase + fs * 4;
        cp16(aDst0, asrc);      cp16(aDst0 + 16, asrc + 4);
        cp16(bDst0, bsrc);      cp16(bDst0 + 16, bsrc + 4);
        CP_COMMIT();
    }

    for (int c = 0; c < 32; ++c) {
        int buf = c & 1;
        if (c + 1 < 32) {
            int k1 = (c + 1) * 16;
            uint32_t aD = smem_u32(&As[buf ^ 1][frow][fs * 4]);
            uint32_t bD = smem_u32(&Bs[buf ^ 1][frow][fs * 4]);
            const float* asrc = g_At + (size_t)(k1 + frow) * NPTS + m0 + fs * 4;
            const float* bsrc = g_Bt + (size_t)(k1 + frow) * KC + nbase + fs * 4;
            cp16(aD, asrc);      cp16(aD + 16, asrc + 4);
            cp16(bD, bsrc);      cp16(bD + 16, bsrc + 4);
            CP_COMMIT();
            CP_WAIT1();
        } else {
            CP_WAIT0();
        }
        __syncthreads();

        #pragma unroll
        for (int kk = 0; kk < 16; kk++) {
            unsigned long long a2[4];
            #pragma unroll
            for (int p = 0; p < 4; p++)
                a2[p] = *(const unsigned long long*)&As[buf][kk][ty * 8 + 2 * p];
            float4 bv0 = *(const float4*)&Bs[buf][kk][tx * 4];
            float4 bv1 = *(const float4*)&Bs[buf][kk][64 + tx * 4];
            float bv[8] = {bv0.x, bv0.y, bv0.z, bv0.w,
                           bv1.x, bv1.y, bv1.z, bv1.w};
            #pragma unroll
            for (int j = 0; j < 8; j++) {
                unsigned long long bd = dup2(bv[j]);
                #pragma unroll
                for (int p = 0; p < 4; p++) ffma2(acc2[p][j], a2[p], bd);
            }
        }
        __syncthreads();
    }

    // distances + argmin. Per-thread col order strictly ascending
    // (j<4: tx*4+j; j>=4: 64+tx*4+(j-4)) => strict < gives first-min.
    float best[8];
    int   bidx[8];
    #pragma unroll
    for (int i = 0; i < 8; i++) { best[i] = FLT_MAX; bidx[i] = 0; }

    #pragma unroll
    for (int j = 0; j < 8; j++) {
        int col = nbase + ((j < 4) ? (tx * 4 + j) : (64 + tx * 4 + (j - 4)));
        float cs = g_csq[col];
        #pragma unroll
        for (int p = 0; p < 4; p++) {
            float d0, d1;
            asm("mov.b64 {%0, %1}, %2;" : "=f"(d0), "=f"(d1) : "l"(acc2[p][j]));
            float dist0 = xr[2 * p]     - 2.0f * d0 + cs;
            float dist1 = xr[2 * p + 1] - 2.0f * d1 + cs;
            if (dist0 < best[2 * p])     { best[2 * p]     = dist0; bidx[2 * p]     = col; }
            if (dist1 < best[2 * p + 1]) { best[2 * p + 1] = dist1; bidx[2 * p + 1] = col; }
        }
    }

    // reduce across 16 tx-lanes (within half-warp), then combine across
    // N-blocks with deterministic packed atomicMin.
    #pragma unroll
    for (int i = 0; i < 8; i++) {
        float bv = best[i];
        int   bi = bidx[i];
        #pragma unroll
        for (int o = 8; o; o >>= 1) {
            float ov = __shfl_xor_sync(0xffffffffu, bv, o);
            int   oi = __shfl_xor_sync(0xffffffffu, bi, o);
            if (ov < bv || (ov == bv && oi < bi)) { bv = ov; bi = oi; }
        }
        if (tx == 0) {
            unsigned int u = __float_as_uint(bv);
            u = (u & 0x80000000u) ? ~u : (u | 0x80000000u);  // order-preserving
            unsigned long long key = ((unsigned long long)u << 32) |
                                     (unsigned int)bi;
            atomicMin(&g_best[m0 + ty * 8 + i], key);
        }
    }
}

// ---------------- clears ----------------
__global__ void k_clear_sums() {
    int i = blockIdx.x * blockDim.x + threadIdx.x;
    if (i < KD) g_sums[i] = 0ull;
    if (i < KC) g_counts[i] = 0;
}
__global__ void k_clear_dacc() {
    int i = blockIdx.x * blockDim.x + threadIdx.x;
    if (i < KD) g_dacc[i] = 0ull;
}

// ---------------- deterministic segment sums ----------------
__global__ void k_accum(const float* __restrict__ feats) {
    int p = blockIdx.x;
    int c = (int)(unsigned int)(g_best[p] & 0xFFFFFFFFull);
    const float* f = feats + (size_t)p * DIM;
    unsigned long long* srow = g_sums + (size_t)c * DIM;
    for (int d = threadIdx.x; d < DIM; d += blockDim.x) {
        long long q = __double2ll_rn((double)f[d] * SCALE_SUM);
        atomicAdd(&srow[d], (unsigned long long)q);
    }
    if (threadIdx.x == 0) atomicAdd(&g_counts[c], 1);
}
__global__ void k_update() {
    int i = blockIdx.x * blockDim.x + threadIdx.x;
    if (i >= KD) return;
    int k   = i >> 9;
    int cnt = g_counts[k];
    if (cnt > 0) {
        double s = (double)(long long)g_sums[i] * (1.0 / SCALE_SUM);
        g_centroids[i] = (float)(s / (double)cnt);
    }
}
__global__ void k_resid(const float* __restrict__ feats) {
    int p = blockIdx.x;
    int c = (int)(unsigned int)(g_best[p] & 0xFFFFFFFFull);
    const float* f  = feats + (size_t)p * DIM;
    const float* cc = g_centroids + (size_t)c * DIM;
    unsigned long long* drow = g_dacc + (size_t)c * DIM;
    for (int d = threadIdx.x; d < DIM; d += blockDim.x) {
        float r  = f[d] - cc[d];
        float r2 = r * r;
        long long q = __double2ll_rn((double)r2 * SCALE_DIST);
        atomicAdd(&drow[d], (unsigned long long)q);
    }
}

// ---------------- final reductions ----------------
__global__ void k_reduce1() {
    __shared__ double sa[256], sb[256];
    int t    = threadIdx.x;
    int base = blockIdx.x * 1024;
    double la = 0.0, lb = 0.0;
    #pragma unroll
    for (int e = 0; e < 4; e++) {
        int i = base + t + e * 256;
        float dist = (float)((double)(long long)g_dacc[i] * (1.0 / SCALE_DIST));
        float p1 = expf(dist * -10.0f);
        float p2 = expf(dist * -10.0f);
        la += (double)p1;
        lb += (double)logf(p2 + 1e-6f);
    }
    sa[t] = la; sb[t] = lb;
    __syncthreads();
    for (int s = 128; s; s >>= 1) {
        if (t < s) { sa[t] += sa[t + s]; sb[t] += sb[t + s]; }
        __syncthreads();
    }
    if (t == 0) { g_pA[blockIdx.x] = sa[0]; g_pB[blockIdx.x] = sb[0]; }
}
__global__ void k_final1() {
    __shared__ double sa[512], sb[512];
    int t = threadIdx.x;
    sa[t] = g_pA[t]; sb[t] = g_pB[t];
    __syncthreads();
    for (int s = 256; s; s >>= 1) {
        if (t < s) { sa[t] += sa[t + s]; sb[t] += sb[t + s]; }
        __syncthreads();
    }
    if (t == 0) { g_scal[0] = sa[0]; g_scal[1] = sb[0]; }
}
__global__ void k_reduce2() {
    __shared__ double sc[256];
    int t    = threadIdx.x;
    int base = blockIdx.x * 1024;
    float S  = (float)g_scal[0];
    double lc = 0.0;
    #pragma unroll
    for (int e = 0; e < 4; e++) {
        int i = base + t + e * 256;
        float dist = (float)((double)(long long)g_dacc[i] * (1.0 / SCALE_DIST));
        float p1 = expf(dist * -10.0f);
        float q  = p1 / S;
        lc += (double)(q * logf(q + 1e-6f));
    }
    sc[t] = lc;
    __syncthreads();
    for (int s = 128; s; s >>= 1) {
        if (t < s) sc[t] += sc[t + s];
        __syncthreads();
    }
    if (t == 0) g_pC[blockIdx.x] = sc[0];
}
__global__ void k_final2(float* __restrict__ out) {
    __shared__ double sc[512];
    int t = threadIdx.x;
    sc[t] = g_pC[t];
    __syncthreads();
    for (int s = 256; s; s >>= 1) {
        if (t < s) sc[t] += sc[t + s];
        __syncthreads();
    }
    if (t == 0) {
        double ent = sc[0] / (double)KD;
        double nll = -(g_scal[1] / (double)KD);
        out[0] = (float)(ent + nll);
    }
}

// ---------------- launch ----------------
extern "C" void kernel_launch(void* const* d_in, const int* in_sizes, int n_in,
                              void* d_out, int out_size) {
    (void)in_sizes; (void)n_in; (void)out_size;
    const float* feats = (const float*)d_in[0];
    float* out = (float*)d_out;

    dim3 tb(32, 8);
    k_xsq<<<NPTS / 8, 256>>>(feats);
    k_copy_init<<<KD / 256, 256>>>(feats);
    k_transpose_A<<<dim3(DIM / 32, NPTS / 32), tb>>>(feats);

    for (int it = 0; it < ITERS; ++it) {
        k_csq<<<KC / 8, 256>>>();
        k_transpose_B<<<dim3(DIM / 32, KC / 32), tb>>>();
        k_clear_best<<<NPTS / 256, 256>>>();
        k_assign<<<dim3(NPTS / 128, KC / 128), 256>>>();
        k_clear_sums<<<KD / 256, 256>>>();
        k_accum<<<NPTS, 128>>>(feats);
        k_update<<<KD / 256, 256>>>();
    }

    k_csq<<<KC / 8, 256>>>();
    k_transpose_B<<<dim3(DIM / 32, KC / 32), tb>>>();
    k_clear_best<<<NPTS / 256, 256>>>();
    k_assign<<<dim3(NPTS / 128, KC / 128), 256>>>();
    k_clear_dacc<<<KD / 256, 256>>>();
    k_resid<<<NPTS, 128>>>(feats);

    k_reduce1<<<512, 256>>>();
    k_final1<<<1, 512>>>();
    k_reduce2<<<512, 256>>>();
    k_final2<<<1, 512>>>(out);
}